// round 1
// baseline (speedup 1.0000x reference)
#include <cuda_runtime.h>

// CrissCrossAttention: B=4, C=512, H=W=128, mid=64, fp32.
// Pipeline:
//  1. proj GEMMs: q = Wq@x, k = Wk@x, v = Wv@x            (per-batch SGEMM)
//  2. tiled transposes: qt,kt,vt (swap H<->W per plane)
//  3. gram GEMMs: eH[b,w,i,j] = sum_m qt*kt ; eW[b,h,i,j] = sum_m q*k
//  4. joint softmax over [eH row ++ eW row] per pixel, diag of eH masked (in-place)
//  5. apply GEMMs: outHt[b,c,w,h] = aH @ vt ; outW -> d_out directly
//  6. combine: out = gamma*(outHt^T + outW) + x  (tiled transpose read)

#define Bsz 4
#define Cch 512
#define MID 64
#define Hd  128
#define Wd  128
#define HWc 16384
#define NEGV (-1e30f)

// ---------------- scratch (static device arrays; no runtime allocation) ----
__device__ float g_q [Bsz*MID*HWc];
__device__ float g_k [Bsz*MID*HWc];
__device__ float g_qt[Bsz*MID*HWc];
__device__ float g_kt[Bsz*MID*HWc];
__device__ float g_v [(size_t)Bsz*Cch*HWc];
__device__ float g_vt[(size_t)Bsz*Cch*HWc];
__device__ float g_outHt[(size_t)Bsz*Cch*HWc];
__device__ float g_eH[(size_t)Bsz*Wd*Hd*Hd];
__device__ float g_eW[(size_t)Bsz*Hd*Wd*Wd];

// ---------------- projection SGEMM: Out[b] = A (MxK) @ X[b] (KxN), N=HW ----
template<int BM, int BN, int BK, int TM, int TN>
__global__ void proj_gemm(const float* __restrict__ A, const float* __restrict__ X,
                          float* __restrict__ Out, int M, int K) {
    constexpr int NT = (BM/TM)*(BN/TN);
    const int N = HWc;
    const int b = blockIdx.z;
    const float* Bp = X + (size_t)b*K*N;
    float* Cp = Out + (size_t)b*M*N;

    __shared__ float As[BK][BM];
    __shared__ float Bs[BK][BN];

    const int tid  = threadIdx.x;
    const int rowA = tid / (BK/4);
    const int colA = tid % (BK/4);
    const int rowB = tid / (BN/4);
    const int colB = tid % (BN/4);
    constexpr int strideA = NT / (BK/4);
    constexpr int strideB = NT / (BN/4);
    const int tr = tid / (BN/TN);
    const int tc = tid % (BN/TN);

    const int aBase = blockIdx.y * BM;
    const int bBase = blockIdx.x * BN;

    float acc[TM][TN] = {};
    float rm[TM], rn[TN];

    for (int k0 = 0; k0 < K; k0 += BK) {
        #pragma unroll
        for (int r = rowA; r < BM; r += strideA) {
            float4 t = *(const float4*)(A + (size_t)(aBase + r)*K + k0 + colA*4);
            As[colA*4+0][r] = t.x; As[colA*4+1][r] = t.y;
            As[colA*4+2][r] = t.z; As[colA*4+3][r] = t.w;
        }
        #pragma unroll
        for (int r = rowB; r < BK; r += strideB) {
            *(float4*)(&Bs[r][colB*4]) =
                *(const float4*)(Bp + (size_t)(k0 + r)*N + bBase + colB*4);
        }
        __syncthreads();
        #pragma unroll
        for (int kk = 0; kk < BK; kk++) {
            #pragma unroll
            for (int m = 0; m < TM; m++) rm[m] = As[kk][tr*TM + m];
            #pragma unroll
            for (int n = 0; n < TN; n++) rn[n] = Bs[kk][tc*TN + n];
            #pragma unroll
            for (int m = 0; m < TM; m++)
                #pragma unroll
                for (int n = 0; n < TN; n++) acc[m][n] += rm[m]*rn[n];
        }
        __syncthreads();
    }
    #pragma unroll
    for (int m = 0; m < TM; m++) {
        float* cr = Cp + (size_t)(aBase + tr*TM + m)*N + bBase + tc*TN;
        #pragma unroll
        for (int n = 0; n < TN; n += 4) {
            float4 t = { acc[m][n], acc[m][n+1], acc[m][n+2], acc[m][n+3] };
            *(float4*)(cr + n) = t;
        }
    }
}

// ---------------- 128x128 per-plane transpose ------------------------------
__global__ void transpose128(const float* __restrict__ in, float* __restrict__ out) {
    __shared__ float t[32][33];
    const size_t p = blockIdx.z;
    const float* ip = in  + p*HWc;
    float*       op = out + p*HWc;
    const int x0 = blockIdx.x*32, y0 = blockIdx.y*32;
    #pragma unroll
    for (int r = 0; r < 32; r += 8)
        t[threadIdx.y + r][threadIdx.x] =
            ip[(size_t)(y0 + threadIdx.y + r)*128 + x0 + threadIdx.x];
    __syncthreads();
    #pragma unroll
    for (int r = 0; r < 32; r += 8)
        op[(size_t)(x0 + threadIdx.y + r)*128 + y0 + threadIdx.x] =
            t[threadIdx.x][threadIdx.y + r];
}

// -------- gram: E[i,j] = sum_m Q(m,i)*K(m,i->j), per (b,line) block ---------
// Q element (m,i) at Qbase[m*HW + i]; 128x128 output, K-dim = MID = 64.
__global__ void gram_gemm(const float* __restrict__ Q, const float* __restrict__ Kp,
                          float* __restrict__ E) {
    const int bl = blockIdx.x;             // b*128 + line
    const int b = bl >> 7, line = bl & 127;
    const float* qb = Q  + (size_t)b*MID*HWc + line*128;
    const float* kb = Kp + (size_t)b*MID*HWc + line*128;

    __shared__ float Qs[16][128];
    __shared__ float Ks[16][128];

    const int tid  = threadIdx.x;
    const int rowL = tid / 32, colL = tid % 32;
    const int tr = tid / 16, tc = tid % 16;

    float acc[8][8] = {};
    float ri[8], rj[8];

    for (int m0 = 0; m0 < MID; m0 += 16) {
        #pragma unroll
        for (int p = 0; p < 2; p++) {
            const int r = rowL + p*8;
            *(float4*)&Qs[r][colL*4] = *(const float4*)(qb + (size_t)(m0 + r)*HWc + colL*4);
            *(float4*)&Ks[r][colL*4] = *(const float4*)(kb + (size_t)(m0 + r)*HWc + colL*4);
        }
        __syncthreads();
        #pragma unroll
        for (int kk = 0; kk < 16; kk++) {
            #pragma unroll
            for (int m = 0; m < 8; m++) ri[m] = Qs[kk][tr*8 + m];
            #pragma unroll
            for (int n = 0; n < 8; n++) rj[n] = Ks[kk][tc*8 + n];
            #pragma unroll
            for (int m = 0; m < 8; m++)
                #pragma unroll
                for (int n = 0; n < 8; n++) acc[m][n] += ri[m]*rj[n];
        }
        __syncthreads();
    }
    float* eb = E + (size_t)bl*HWc;
    #pragma unroll
    for (int m = 0; m < 8; m++) {
        float* er = eb + (size_t)(tr*8 + m)*128 + tc*8;
        #pragma unroll
        for (int n = 0; n < 8; n += 4) {
            float4 t = { acc[m][n], acc[m][n+1], acc[m][n+2], acc[m][n+3] };
            *(float4*)(er + n) = t;
        }
    }
}

// -------- joint softmax over 256 scores per pixel, one warp per pixel ------
__global__ void softmax_kernel(float* __restrict__ eH, float* __restrict__ eW) {
    const int pix  = blockIdx.x*8 + (threadIdx.x >> 5);
    const int lane = threadIdx.x & 31;
    const int w = pix & 127, h = (pix >> 7) & 127, b = pix >> 14;

    float* ph = eH + ((size_t)((b*128 + w)*128 + h))*128 + lane*4;
    float* pw = eW + ((size_t)((b*128 + h)*128 + w))*128 + lane*4;
    float4 vh = *(float4*)ph;
    float4 vw = *(float4*)pw;

    const int d = h - lane*4;           // diag mask on eH at j == h
    if (d >= 0 && d < 4) ((float*)&vh)[d] = NEGV;

    float mx = fmaxf(fmaxf(fmaxf(vh.x, vh.y), fmaxf(vh.z, vh.w)),
                     fmaxf(fmaxf(vw.x, vw.y), fmaxf(vw.z, vw.w)));
    #pragma unroll
    for (int o = 16; o; o >>= 1) mx = fmaxf(mx, __shfl_xor_sync(0xffffffffu, mx, o));

    vh.x = __expf(vh.x - mx); vh.y = __expf(vh.y - mx);
    vh.z = __expf(vh.z - mx); vh.w = __expf(vh.w - mx);
    vw.x = __expf(vw.x - mx); vw.y = __expf(vw.y - mx);
    vw.z = __expf(vw.z - mx); vw.w = __expf(vw.w - mx);

    float s = vh.x + vh.y + vh.z + vh.w + vw.x + vw.y + vw.z + vw.w;
    #pragma unroll
    for (int o = 16; o; o >>= 1) s += __shfl_xor_sync(0xffffffffu, s, o);
    const float inv = 1.0f / s;

    vh.x *= inv; vh.y *= inv; vh.z *= inv; vh.w *= inv;
    vw.x *= inv; vw.y *= inv; vw.z *= inv; vw.w *= inv;
    *(float4*)ph = vh;
    *(float4*)pw = vw;
}

// -------- apply: Out(c,i) = sum_j V(c,j) * A(i,j), per (b,line) -------------
// V element (c,j) at Vb[c*HW + j]; Out element (c,i) at Ob[c*HW + i].
__global__ void apply_gemm(const float* __restrict__ V, const float* __restrict__ Aattn,
                           float* __restrict__ Out) {
    const int bl = blockIdx.y;            // b*128 + line
    const int b = bl >> 7, line = bl & 127;
    const float* Vb = V + (size_t)b*Cch*HWc + line*128;
    const float* Ab = Aattn + (size_t)bl*HWc;
    float* Ob = Out + (size_t)b*Cch*HWc + line*128;
    const int c0 = blockIdx.x * 128;

    __shared__ float Vs[16][128];   // [j_local][c_local]
    __shared__ float As[16][128];   // [j_local][i]

    const int tid  = threadIdx.x;
    const int rowL = tid / 4, colL = tid % 4;
    const int tr = tid / 16, tc = tid % 16;

    float acc[8][8] = {};
    float rv[8], ra[8];

    for (int j0 = 0; j0 < 128; j0 += 16) {
        #pragma unroll
        for (int p = 0; p < 2; p++) {
            const int r = rowL + p*64;
            float4 t = *(const float4*)(Vb + (size_t)(c0 + r)*HWc + j0 + colL*4);
            Vs[colL*4+0][r] = t.x; Vs[colL*4+1][r] = t.y;
            Vs[colL*4+2][r] = t.z; Vs[colL*4+3][r] = t.w;
            float4 a = *(const float4*)(Ab + (size_t)r*128 + j0 + colL*4);
            As[colL*4+0][r] = a.x; As[colL*4+1][r] = a.y;
            As[colL*4+2][r] = a.z; As[colL*4+3][r] = a.w;
        }
        __syncthreads();
        #pragma unroll
        for (int kk = 0; kk < 16; kk++) {
            #pragma unroll
            for (int m = 0; m < 8; m++) rv[m] = Vs[kk][tr*8 + m];
            #pragma unroll
            for (int n = 0; n < 8; n++) ra[n] = As[kk][tc*8 + n];
            #pragma unroll
            for (int m = 0; m < 8; m++)
                #pragma unroll
                for (int n = 0; n < 8; n++) acc[m][n] += rv[m]*ra[n];
        }
        __syncthreads();
    }
    #pragma unroll
    for (int m = 0; m < 8; m++) {
        float* orow = Ob + (size_t)(c0 + tr*8 + m)*HWc + tc*8;
        #pragma unroll
        for (int n = 0; n < 8; n += 4) {
            float4 t = { acc[m][n], acc[m][n+1], acc[m][n+2], acc[m][n+3] };
            *(float4*)(orow + n) = t;
        }
    }
}

// -------- combine: out = gamma*(outHt^T + outW) + x -------------------------
__global__ void combine_kernel(const float* __restrict__ outHt, const float* __restrict__ outW,
                               const float* __restrict__ x, const float* __restrict__ gamma,
                               float* __restrict__ out) {
    __shared__ float t[32][33];
    const size_t p = blockIdx.z;
    const float* hp = outHt + p*HWc;
    const int w0 = blockIdx.x*32, h0 = blockIdx.y*32;
    #pragma unroll
    for (int r = 0; r < 32; r += 8)
        t[threadIdx.y + r][threadIdx.x] =
            hp[(size_t)(w0 + threadIdx.y + r)*128 + h0 + threadIdx.x];
    __syncthreads();
    const float g = gamma[0];
    #pragma unroll
    for (int r = 0; r < 32; r += 8) {
        const int h = h0 + threadIdx.y + r;
        const int w = w0 + threadIdx.x;
        const size_t idx = p*HWc + (size_t)h*128 + w;
        out[idx] = g*(t[threadIdx.x][threadIdx.y + r] + outW[idx]) + x[idx];
    }
}

// ---------------------------------------------------------------------------
extern "C" void kernel_launch(void* const* d_in, const int* in_sizes, int n_in,
                              void* d_out, int out_size) {
    (void)in_sizes; (void)n_in; (void)out_size;
    const float* x     = (const float*)d_in[0];
    const float* Wq    = (const float*)d_in[1];
    const float* Wk    = (const float*)d_in[2];
    const float* Wv    = (const float*)d_in[3];
    const float* gamma = (const float*)d_in[4];
    float* out = (float*)d_out;

    float *q, *k, *qt, *kt, *v, *vt, *outHt, *eH, *eW;
    cudaGetSymbolAddress((void**)&q,  g_q);
    cudaGetSymbolAddress((void**)&k,  g_k);
    cudaGetSymbolAddress((void**)&qt, g_qt);
    cudaGetSymbolAddress((void**)&kt, g_kt);
    cudaGetSymbolAddress((void**)&v,  g_v);
    cudaGetSymbolAddress((void**)&vt, g_vt);
    cudaGetSymbolAddress((void**)&outHt, g_outHt);
    cudaGetSymbolAddress((void**)&eH, g_eH);
    cudaGetSymbolAddress((void**)&eW, g_eW);

    // 1) projections
    proj_gemm< 64,128,16,8,8><<<dim3(HWc/128, 1, Bsz), 128>>>(Wq, x, q, MID, Cch);
    proj_gemm< 64,128,16,8,8><<<dim3(HWc/128, 1, Bsz), 128>>>(Wk, x, k, MID, Cch);
    proj_gemm<128,128,16,8,8><<<dim3(HWc/128, Cch/128, Bsz), 256>>>(Wv, x, v, Cch, Cch);

    // 2) transposes (H<->W per plane)
    transpose128<<<dim3(4,4,Bsz*MID), dim3(32,8)>>>(q, qt);
    transpose128<<<dim3(4,4,Bsz*MID), dim3(32,8)>>>(k, kt);
    transpose128<<<dim3(4,4,Bsz*Cch), dim3(32,8)>>>(v, vt);

    // 3) attention scores
    gram_gemm<<<Bsz*Wd, 256>>>(qt, kt, eH);   // eH[b,w,i,j]
    gram_gemm<<<Bsz*Hd, 256>>>(q,  k,  eW);   // eW[b,h,i,j]

    // 4) joint softmax (in-place, diag of eH masked)
    softmax_kernel<<<(Bsz*HWc)/8, 256>>>(eH, eW);

    // 5) apply attention
    apply_gemm<<<dim3(Cch/128, Bsz*Wd), 256>>>(vt, eH, outHt); // outHt[b,c,w,h]
    apply_gemm<<<dim3(Cch/128, Bsz*Hd), 256>>>(v,  eW, out);   // outW straight into d_out

    // 6) combine
    combine_kernel<<<dim3(4,4,Bsz*Cch), dim3(32,8)>>>(outHt, out, x, gamma, out);
}

// round 3
// speedup vs baseline: 2.4372x; 2.4372x over previous
#include <cuda_runtime.h>
#include <cstdint>

#define Bsz 4
#define Cch 512
#define MID 64
#define HWc 16384
#define PROJ_M 640
#define NEGV (-1e30f)

// ---------------- scratch ----------------------------------------------------
__device__ __align__(16) float g_proj [(size_t)Bsz*PROJ_M*HWc];
__device__ __align__(16) float g_projT[(size_t)Bsz*PROJ_M*HWc];
__device__ __align__(16) float g_eH[(size_t)Bsz*128*HWc];
__device__ __align__(16) float g_eW[(size_t)Bsz*128*HWc];
__device__ __align__(16) float g_outHt[(size_t)Bsz*Cch*HWc];

// ---------------- tf32 helpers ------------------------------------------------
__device__ __forceinline__ uint32_t f2t(float f){
    uint32_t r; asm("cvt.rna.tf32.f32 %0, %1;" : "=r"(r) : "f"(f)); return r;
}
__device__ __forceinline__ uint4 cvt4(float4 v){
    uint4 u; u.x=f2t(v.x); u.y=f2t(v.y); u.z=f2t(v.z); u.w=f2t(v.w); return u;
}
__device__ __forceinline__ void mma_tf32(float* c, const uint32_t* a, uint32_t b0, uint32_t b1){
    asm volatile(
        "mma.sync.aligned.m16n8k8.row.col.f32.tf32.tf32.f32 "
        "{%0,%1,%2,%3}, {%4,%5,%6,%7}, {%8,%9}, {%0,%1,%2,%3};"
        : "+f"(c[0]),"+f"(c[1]),"+f"(c[2]),"+f"(c[3])
        : "r"(a[0]),"r"(a[1]),"r"(a[2]),"r"(a[3]),"r"(b0),"r"(b1));
}

// ---------------- projection: proj[b] = Wall(640x512) @ x[b](512x16384) ------
// Wall rows: [0,64)=Wq, [64,128)=Wk, [128,640)=Wv — read directly from the 3 inputs.
// block 128x128, BK=16, 256 thr, warps 2x4, warp tile 64x32.
__global__ void proj_tf32(const float* __restrict__ Wq, const float* __restrict__ Wk,
                          const float* __restrict__ Wv, const float* __restrict__ X,
                          float* __restrict__ Out){
    const int b = blockIdx.z;
    const int m0blk = blockIdx.y * 128;
    const float* Bg = X + (size_t)b*Cch*HWc + blockIdx.x*128;
    float* Cg = Out + ((size_t)b*PROJ_M + m0blk)*HWc + blockIdx.x*128;

    __shared__ uint32_t As[128*20];   // [m][k], stride 20
    __shared__ uint32_t Bs[16*136];   // [k][n], stride 136

    const int tid = threadIdx.x, lane = tid & 31, warp = tid >> 5;
    const int g = lane >> 2, t4 = lane & 3;
    const int wr = warp >> 2, wc = warp & 3;

    float acc[4][4][4] = {};

    for (int k0 = 0; k0 < Cch; k0 += 16){
        #pragma unroll
        for (int i = 0; i < 2; i++){
            int e = tid + i*256, r = e >> 2, c = e & 3;
            int grow = m0blk + r;   // global W row
            const float* src = grow < 64  ? Wq + (size_t)grow*Cch
                             : grow < 128 ? Wk + (size_t)(grow-64)*Cch
                                          : Wv + (size_t)(grow-128)*Cch;
            *(uint4*)&As[r*20 + c*4] = cvt4(*(const float4*)(src + k0 + c*4));
        }
        #pragma unroll
        for (int i = 0; i < 2; i++){
            int e = tid + i*256, r = e >> 5, c = e & 31;
            *(uint4*)&Bs[r*136 + c*4] = cvt4(*(const float4*)(Bg + (size_t)(k0+r)*HWc + c*4));
        }
        __syncthreads();
        #pragma unroll
        for (int ks = 0; ks < 2; ks++){
            uint32_t a[4][4], bb[4][2];
            #pragma unroll
            for (int mt = 0; mt < 4; mt++){
                int rb = wr*64 + mt*16;
                a[mt][0] = As[(rb+g)*20   + ks*8 + t4];
                a[mt][1] = As[(rb+g+8)*20 + ks*8 + t4];
                a[mt][2] = As[(rb+g)*20   + ks*8 + t4 + 4];
                a[mt][3] = As[(rb+g+8)*20 + ks*8 + t4 + 4];
            }
            #pragma unroll
            for (int nt = 0; nt < 4; nt++){
                int nb = wc*32 + nt*8;
                bb[nt][0] = Bs[(ks*8+t4)*136   + nb + g];
                bb[nt][1] = Bs[(ks*8+t4+4)*136 + nb + g];
            }
            #pragma unroll
            for (int mt = 0; mt < 4; mt++)
                #pragma unroll
                for (int nt = 0; nt < 4; nt++)
                    mma_tf32(acc[mt][nt], a[mt], bb[nt][0], bb[nt][1]);
        }
        __syncthreads();
    }
    #pragma unroll
    for (int mt = 0; mt < 4; mt++)
        #pragma unroll
        for (int nt = 0; nt < 4; nt++){
            int row = wr*64 + mt*16 + g;
            int col = wc*32 + nt*8 + t4*2;
            float2 u0 = { acc[mt][nt][0], acc[mt][nt][1] };
            float2 u1 = { acc[mt][nt][2], acc[mt][nt][3] };
            *(float2*)(Cg + (size_t)row*HWc + col)     = u0;
            *(float2*)(Cg + (size_t)(row+8)*HWc + col) = u1;
        }
}

// ---------------- 128x128 per-plane fp32 transpose ----------------------------
__global__ void transpose128(const float* __restrict__ in, float* __restrict__ out) {
    __shared__ float t[32][33];
    const size_t p = blockIdx.z;
    const float* ip = in  + p*HWc;
    float*       op = out + p*HWc;
    const int x0 = blockIdx.x*32, y0 = blockIdx.y*32;
    #pragma unroll
    for (int r = 0; r < 32; r += 8)
        t[threadIdx.y + r][threadIdx.x] =
            ip[(size_t)(y0 + threadIdx.y + r)*128 + x0 + threadIdx.x];
    __syncthreads();
    #pragma unroll
    for (int r = 0; r < 32; r += 8)
        op[(size_t)(x0 + threadIdx.y + r)*128 + y0 + threadIdx.x] =
            t[threadIdx.x][threadIdx.y + r];
}

// ---------------- gram: E[i,j] = sum_m Q[m,i]*K[m,j], per (b,line) ------------
// 128x128 out, K=64; block 256 thr, warps 2x4, warp tile 64x32, BM-chunk 32.
__global__ void gram_tf32(const float* __restrict__ P, float* __restrict__ E){
    const int bl = blockIdx.x, b = bl >> 7, line = bl & 127;
    const float* qb = P + (size_t)(b*PROJ_M)*HWc + line*128;
    const float* kb = qb + (size_t)MID*HWc;

    __shared__ uint32_t Qs[32*136];   // [m][i]
    __shared__ uint32_t Ks[32*136];   // [m][j]

    const int tid = threadIdx.x, lane = tid & 31, warp = tid >> 5;
    const int g = lane >> 2, t4 = lane & 3;
    const int wr = warp >> 2, wc = warp & 3;

    float acc[4][4][4] = {};

    for (int m0 = 0; m0 < MID; m0 += 32){
        #pragma unroll
        for (int i = 0; i < 4; i++){
            int e = tid + i*256, r = e >> 5, c = e & 31;
            *(uint4*)&Qs[r*136 + c*4] = cvt4(*(const float4*)(qb + (size_t)(m0+r)*HWc + c*4));
            *(uint4*)&Ks[r*136 + c*4] = cvt4(*(const float4*)(kb + (size_t)(m0+r)*HWc + c*4));
        }
        __syncthreads();
        #pragma unroll
        for (int ks = 0; ks < 4; ks++){
            uint32_t a[4][4], bb[4][2];
            #pragma unroll
            for (int mt = 0; mt < 4; mt++){
                int rb = wr*64 + mt*16;
                a[mt][0] = Qs[(ks*8+t4)*136   + rb + g];
                a[mt][1] = Qs[(ks*8+t4)*136   + rb + g + 8];
                a[mt][2] = Qs[(ks*8+t4+4)*136 + rb + g];
                a[mt][3] = Qs[(ks*8+t4+4)*136 + rb + g + 8];
            }
            #pragma unroll
            for (int nt = 0; nt < 4; nt++){
                int nb = wc*32 + nt*8;
                bb[nt][0] = Ks[(ks*8+t4)*136   + nb + g];
                bb[nt][1] = Ks[(ks*8+t4+4)*136 + nb + g];
            }
            #pragma unroll
            for (int mt = 0; mt < 4; mt++)
                #pragma unroll
                for (int nt = 0; nt < 4; nt++)
                    mma_tf32(acc[mt][nt], a[mt], bb[nt][0], bb[nt][1]);
        }
        __syncthreads();
    }
    float* eb = E + (size_t)bl*HWc;
    #pragma unroll
    for (int mt = 0; mt < 4; mt++)
        #pragma unroll
        for (int nt = 0; nt < 4; nt++){
            int row = wr*64 + mt*16 + g;
            int col = wc*32 + nt*8 + t4*2;
            float2 u0 = { acc[mt][nt][0], acc[mt][nt][1] };
            float2 u1 = { acc[mt][nt][2], acc[mt][nt][3] };
            *(float2*)&eb[(size_t)row*128 + col]     = u0;
            *(float2*)&eb[(size_t)(row+8)*128 + col] = u1;
        }
}

// ---------------- joint softmax over 256 scores, in-place fp32 ----------------
__global__ void softmax_kernel(float* __restrict__ eH, float* __restrict__ eW) {
    const int pix  = blockIdx.x*8 + (threadIdx.x >> 5);
    const int lane = threadIdx.x & 31;
    const int w = pix & 127, h = (pix >> 7) & 127, b = pix >> 14;

    float* ph = eH + ((size_t)((b*128 + w)*128 + h))*128 + lane*4;
    float* pw = eW + ((size_t)((b*128 + h)*128 + w))*128 + lane*4;
    float4 vh = *(float4*)ph;
    float4 vw = *(float4*)pw;

    const int d = h - lane*4;
    if (d >= 0 && d < 4) ((float*)&vh)[d] = NEGV;

    float mx = fmaxf(fmaxf(fmaxf(vh.x, vh.y), fmaxf(vh.z, vh.w)),
                     fmaxf(fmaxf(vw.x, vw.y), fmaxf(vw.z, vw.w)));
    #pragma unroll
    for (int o = 16; o; o >>= 1) mx = fmaxf(mx, __shfl_xor_sync(0xffffffffu, mx, o));

    vh.x = __expf(vh.x - mx); vh.y = __expf(vh.y - mx);
    vh.z = __expf(vh.z - mx); vh.w = __expf(vh.w - mx);
    vw.x = __expf(vw.x - mx); vw.y = __expf(vw.y - mx);
    vw.z = __expf(vw.z - mx); vw.w = __expf(vw.w - mx);

    float s = vh.x + vh.y + vh.z + vh.w + vw.x + vw.y + vw.z + vw.w;
    #pragma unroll
    for (int o = 16; o; o >>= 1) s += __shfl_xor_sync(0xffffffffu, s, o);
    const float inv = 1.0f / s;

    vh.x *= inv; vh.y *= inv; vh.z *= inv; vh.w *= inv;
    vw.x *= inv; vw.y *= inv; vw.z *= inv; vw.w *= inv;
    *(float4*)ph = vh;
    *(float4*)pw = vw;
}

// ---------------- apply: Out[c,i] = sum_j V[c,j]*P[i,j], per (b,line) ---------
// block 128c x 128i, K=128; 256 thr, warps 2x4, warp tile 64x32, BK=32.
__global__ void apply_tf32(const float* __restrict__ Vfull, const float* __restrict__ P,
                           float* __restrict__ Out){
    const int bl = blockIdx.y, b = bl >> 7, line = bl & 127;
    const float* Vb = Vfull + ((size_t)(b*PROJ_M + 128 + blockIdx.x*128))*HWc + line*128;
    const float* Pb = P + (size_t)bl*HWc;
    float* Ob = Out + ((size_t)(b*Cch + blockIdx.x*128))*HWc + line*128;

    __shared__ uint32_t Vs[128*36];   // [c][j], stride 36
    __shared__ uint32_t Ps[128*36];   // [i][j], stride 36

    const int tid = threadIdx.x, lane = tid & 31, warp = tid >> 5;
    const int g = lane >> 2, t4 = lane & 3;
    const int wr = warp >> 2, wc = warp & 3;

    float acc[4][4][4] = {};

    for (int j0 = 0; j0 < 128; j0 += 32){
        #pragma unroll
        for (int i = 0; i < 4; i++){
            int e = tid + i*256, r = e >> 3, c = e & 7;
            *(uint4*)&Vs[r*36 + c*4] = cvt4(*(const float4*)(Vb + (size_t)r*HWc + j0 + c*4));
            *(uint4*)&Ps[r*36 + c*4] = cvt4(*(const float4*)(Pb + (size_t)r*128 + j0 + c*4));
        }
        __syncthreads();
        #pragma unroll
        for (int ks = 0; ks < 4; ks++){
            uint32_t a[4][4], bb[4][2];
            #pragma unroll
            for (int mt = 0; mt < 4; mt++){
                int rb = wr*64 + mt*16;
                a[mt][0] = Vs[(rb+g)*36   + ks*8 + t4];
                a[mt][1] = Vs[(rb+g+8)*36 + ks*8 + t4];
                a[mt][2] = Vs[(rb+g)*36   + ks*8 + t4 + 4];
                a[mt][3] = Vs[(rb+g+8)*36 + ks*8 + t4 + 4];
            }
            #pragma unroll
            for (int nt = 0; nt < 4; nt++){
                int nb = wc*32 + nt*8;
                bb[nt][0] = Ps[(nb+g)*36 + ks*8 + t4];
                bb[nt][1] = Ps[(nb+g)*36 + ks*8 + t4 + 4];
            }
            #pragma unroll
            for (int mt = 0; mt < 4; mt++)
                #pragma unroll
                for (int nt = 0; nt < 4; nt++)
                    mma_tf32(acc[mt][nt], a[mt], bb[nt][0], bb[nt][1]);
        }
        __syncthreads();
    }
    #pragma unroll
    for (int mt = 0; mt < 4; mt++)
        #pragma unroll
        for (int nt = 0; nt < 4; nt++){
            int row = wr*64 + mt*16 + g;
            int col = wc*32 + nt*8 + t4*2;
            float2 u0 = { acc[mt][nt][0], acc[mt][nt][1] };
            float2 u1 = { acc[mt][nt][2], acc[mt][nt][3] };
            *(float2*)(Ob + (size_t)row*HWc + col)     = u0;
            *(float2*)(Ob + (size_t)(row+8)*HWc + col) = u1;
        }
}

// ---------------- combine: out = gamma*(outHt^T + outW) + x -------------------
__global__ void combine_kernel(const float* __restrict__ outHt, const float* __restrict__ outW,
                               const float* __restrict__ x, const float* __restrict__ gamma,
                               float* __restrict__ out) {
    __shared__ float t[32][33];
    const size_t p = blockIdx.z;
    const float* hp = outHt + p*HWc;
    const int w0 = blockIdx.x*32, h0 = blockIdx.y*32;
    #pragma unroll
    for (int r = 0; r < 32; r += 8)
        t[threadIdx.y + r][threadIdx.x] =
            hp[(size_t)(w0 + threadIdx.y + r)*128 + h0 + threadIdx.x];
    __syncthreads();
    const float g = gamma[0];
    #pragma unroll
    for (int r = 0; r < 32; r += 8) {
        const int h = h0 + threadIdx.y + r;
        const int w = w0 + threadIdx.x;
        const size_t idx = p*HWc + (size_t)h*128 + w;
        out[idx] = g*(t[threadIdx.x][threadIdx.y + r] + outW[idx]) + x[idx];
    }
}

// ---------------------------------------------------------------------------
extern "C" void kernel_launch(void* const* d_in, const int* in_sizes, int n_in,
                              void* d_out, int out_size) {
    (void)in_sizes; (void)n_in; (void)out_size;
    const float* x     = (const float*)d_in[0];
    const float* Wq    = (const float*)d_in[1];
    const float* Wk    = (const float*)d_in[2];
    const float* Wv    = (const float*)d_in[3];
    const float* gamma = (const float*)d_in[4];
    float* out = (float*)d_out;

    float *proj, *projT, *eH, *eW, *outHt;
    cudaGetSymbolAddress((void**)&proj,  g_proj);
    cudaGetSymbolAddress((void**)&projT, g_projT);
    cudaGetSymbolAddress((void**)&eH,    g_eH);
    cudaGetSymbolAddress((void**)&eW,    g_eW);
    cudaGetSymbolAddress((void**)&outHt, g_outHt);

    // 1) fused projection (q|k|v packed: 640 planes per batch)
    proj_tf32<<<dim3(HWc/128, PROJ_M/128, Bsz), 256>>>(Wq, Wk, Wv, x, proj);

    // 2) plane transposes (H<->W for all 640 planes per batch)
    transpose128<<<dim3(4,4,Bsz*PROJ_M), dim3(32,8)>>>(proj, projT);

    // 3) attention scores
    gram_tf32<<<Bsz*128, 256>>>(projT, eH);   // eH[b,w,i=h,j=h']
    gram_tf32<<<Bsz*128, 256>>>(proj,  eW);   // eW[b,h,i=w,j=w']

    // 4) joint softmax (in-place, diag of eH masked)
    softmax_kernel<<<(Bsz*HWc)/8, 256>>>(eH, eW);

    // 5) apply attention
    apply_tf32<<<dim3(Cch/128, Bsz*128), 256>>>(projT, eH, outHt); // outHt[b,c,w,h]
    apply_tf32<<<dim3(Cch/128, Bsz*128), 256>>>(proj,  eW, out);   // outW -> d_out

    // 6) combine
    combine_kernel<<<dim3(4,4,Bsz*Cch), dim3(32,8)>>>(outHt, out, x, gamma, out);
}

// round 4
// speedup vs baseline: 2.8382x; 1.1646x over previous
#include <cuda_runtime.h>
#include <cstdint>

#define Bsz 4
#define Cch 512
#define MID 64
#define HWc 16384
#define PROJ_M 640
#define NEGV (-1e30f)

// ---------------- scratch ----------------------------------------------------
__device__ __align__(16) float g_proj [(size_t)Bsz*PROJ_M*HWc];
__device__ __align__(16) float g_projT[(size_t)Bsz*PROJ_M*HWc];
__device__ __align__(16) float g_eH[(size_t)Bsz*128*HWc];
__device__ __align__(16) float g_eW[(size_t)Bsz*128*HWc];
__device__ __align__(16) float g_outHt[(size_t)Bsz*Cch*HWc];

// ---------------- helpers ------------------------------------------------------
__device__ __forceinline__ uint32_t f2t(float f){
    uint32_t r; asm("cvt.rna.tf32.f32 %0, %1;" : "=r"(r) : "f"(f)); return r;
}
__device__ __forceinline__ uint4 cvt4(float4 v){
    uint4 u; u.x=f2t(v.x); u.y=f2t(v.y); u.z=f2t(v.z); u.w=f2t(v.w); return u;
}
__device__ __forceinline__ void mma_tf32(float* c, const uint32_t* a, uint32_t b0, uint32_t b1){
    asm volatile(
        "mma.sync.aligned.m16n8k8.row.col.f32.tf32.tf32.f32 "
        "{%0,%1,%2,%3}, {%4,%5,%6,%7}, {%8,%9}, {%0,%1,%2,%3};"
        : "+f"(c[0]),"+f"(c[1]),"+f"(c[2]),"+f"(c[3])
        : "r"(a[0]),"r"(a[1]),"r"(a[2]),"r"(a[3]),"r"(b0),"r"(b1));
}
__device__ __forceinline__ uint32_t sptr(const void* p){
    return (uint32_t)__cvta_generic_to_shared(p);
}
__device__ __forceinline__ void cpa16(uint32_t s, const void* g){
    asm volatile("cp.async.ca.shared.global [%0], [%1], 16;" :: "r"(s), "l"(g));
}
#define CP_COMMIT() asm volatile("cp.async.commit_group;")
#define CP_WAIT(n)  asm volatile("cp.async.wait_group %0;" :: "n"(n))

// ---------------- projection: proj[b] = Wall(640x512) @ x[b](512x16384) ------
// block 128x128, BK=16, 2-stage cp.async; 256 thr, warps 2x4, warp tile 64x32.
__global__ void proj_tf32(const float* __restrict__ Wq, const float* __restrict__ Wk,
                          const float* __restrict__ Wv, const float* __restrict__ X,
                          float* __restrict__ Out){
    const int b = blockIdx.z;
    const int m0blk = blockIdx.y * 128;
    const float* Bg = X + (size_t)b*Cch*HWc + blockIdx.x*128;
    float* Cg = Out + ((size_t)b*PROJ_M + m0blk)*HWc + blockIdx.x*128;

    __shared__ float As[2][128*20];   // [m][k] stride 20
    __shared__ float Bs[2][16*136];   // [k][n] stride 136

    const int tid = threadIdx.x, lane = tid & 31, warp = tid >> 5;
    const int g = lane >> 2, t4 = lane & 3;
    const int wr = warp >> 2, wc = warp & 3;

    // per-thread load slots (fixed rows across k-loop)
    const float* arow[2]; uint32_t adst[2][2];
    const float* brow[2]; uint32_t bdst[2][2];
    #pragma unroll
    for (int i = 0; i < 2; i++){
        int e = tid + i*256;
        int r = e >> 2, c = e & 3;
        int grow = m0blk + r;
        arow[i] = (grow < 64  ? Wq + (size_t)grow*Cch
                 : grow < 128 ? Wk + (size_t)(grow-64)*Cch
                              : Wv + (size_t)(grow-128)*Cch) + c*4;
        adst[0][i] = sptr(&As[0][r*20 + c*4]);
        adst[1][i] = sptr(&As[1][r*20 + c*4]);
        int rb2 = e >> 5, cb = e & 31;
        brow[i] = Bg + (size_t)rb2*HWc + cb*4;
        bdst[0][i] = sptr(&Bs[0][rb2*136 + cb*4]);
        bdst[1][i] = sptr(&Bs[1][rb2*136 + cb*4]);
    }

    float acc[4][4][4] = {};
    const int NIT = Cch/16;

    // prologue: stage 0
    #pragma unroll
    for (int i = 0; i < 2; i++){
        cpa16(adst[0][i], arow[i]);
        cpa16(bdst[0][i], brow[i]);
    }
    CP_COMMIT();

    for (int it = 0; it < NIT; it++){
        const int cur = it & 1;
        if (it + 1 < NIT){
            const int nxt = cur ^ 1;
            const int k0 = (it+1)*16;
            #pragma unroll
            for (int i = 0; i < 2; i++){
                cpa16(adst[nxt][i], arow[i] + k0);
                cpa16(bdst[nxt][i], brow[i] + (size_t)k0*HWc);
            }
            CP_COMMIT();
            CP_WAIT(1);
        } else {
            CP_WAIT(0);
        }
        __syncthreads();
        const float* Ac = As[cur];
        const float* Bc = Bs[cur];
        #pragma unroll
        for (int ks = 0; ks < 2; ks++){
            uint32_t a[4][4], bb[4][2];
            #pragma unroll
            for (int mt = 0; mt < 4; mt++){
                int rb = wr*64 + mt*16;
                a[mt][0] = __float_as_uint(Ac[(rb+g)*20   + ks*8 + t4]);
                a[mt][1] = __float_as_uint(Ac[(rb+g+8)*20 + ks*8 + t4]);
                a[mt][2] = __float_as_uint(Ac[(rb+g)*20   + ks*8 + t4 + 4]);
                a[mt][3] = __float_as_uint(Ac[(rb+g+8)*20 + ks*8 + t4 + 4]);
            }
            #pragma unroll
            for (int nt = 0; nt < 4; nt++){
                int nb = wc*32 + nt*8;
                bb[nt][0] = __float_as_uint(Bc[(ks*8+t4)*136   + nb + g]);
                bb[nt][1] = __float_as_uint(Bc[(ks*8+t4+4)*136 + nb + g]);
            }
            #pragma unroll
            for (int mt = 0; mt < 4; mt++)
                #pragma unroll
                for (int nt = 0; nt < 4; nt++)
                    mma_tf32(acc[mt][nt], a[mt], bb[nt][0], bb[nt][1]);
        }
        __syncthreads();
    }
    #pragma unroll
    for (int mt = 0; mt < 4; mt++)
        #pragma unroll
        for (int nt = 0; nt < 4; nt++){
            int row = wr*64 + mt*16 + g;
            int col = wc*32 + nt*8 + t4*2;
            float2 u0 = { acc[mt][nt][0], acc[mt][nt][1] };
            float2 u1 = { acc[mt][nt][2], acc[mt][nt][3] };
            *(float2*)(Cg + (size_t)row*HWc + col)     = u0;
            *(float2*)(Cg + (size_t)(row+8)*HWc + col) = u1;
        }
}

// ---------------- 128x128 per-plane fp32 transpose, 64x64 float4 tiles --------
__global__ void transpose128v(const float* __restrict__ in, float* __restrict__ out){
    __shared__ float t[64][65];
    const size_t p = blockIdx.z;
    const float* ip = in  + p*HWc;
    float*       op = out + p*HWc;
    const int x0 = blockIdx.x*64, y0 = blockIdx.y*64;
    const int tx = threadIdx.x & 15, ty = threadIdx.x >> 4;
    #pragma unroll
    for (int r = 0; r < 64; r += 16){
        float4 v = *(const float4*)(ip + (size_t)(y0+ty+r)*128 + x0 + tx*4);
        float* d = &t[ty+r][tx*4];
        d[0]=v.x; d[1]=v.y; d[2]=v.z; d[3]=v.w;
    }
    __syncthreads();
    #pragma unroll
    for (int r = 0; r < 64; r += 16){
        float4 o = { t[tx*4+0][ty+r], t[tx*4+1][ty+r],
                     t[tx*4+2][ty+r], t[tx*4+3][ty+r] };
        *(float4*)(op + (size_t)(x0+ty+r)*128 + y0 + tx*4) = o;
    }
}

// ---------------- gram: E[i,j] = sum_m Q[m,i]*K[m,j], per (b,line,dir) --------
// blockIdx.y: 0 -> eH from projT, 1 -> eW from proj
__global__ void gram_tf32(const float* __restrict__ proj, const float* __restrict__ projT,
                          float* __restrict__ eH, float* __restrict__ eW){
    const float* P = blockIdx.y ? proj : projT;
    float* E = blockIdx.y ? eW : eH;
    const int bl = blockIdx.x, b = bl >> 7, line = bl & 127;
    const float* qb = P + (size_t)(b*PROJ_M)*HWc + line*128;
    const float* kb = qb + (size_t)MID*HWc;

    __shared__ uint32_t Qs[32*136];
    __shared__ uint32_t Ks[32*136];

    const int tid = threadIdx.x, lane = tid & 31, warp = tid >> 5;
    const int g = lane >> 2, t4 = lane & 3;
    const int wr = warp >> 2, wc = warp & 3;

    float acc[4][4][4] = {};

    for (int m0 = 0; m0 < MID; m0 += 32){
        #pragma unroll
        for (int i = 0; i < 4; i++){
            int e = tid + i*256, r = e >> 5, c = e & 31;
            *(uint4*)&Qs[r*136 + c*4] = cvt4(*(const float4*)(qb + (size_t)(m0+r)*HWc + c*4));
            *(uint4*)&Ks[r*136 + c*4] = cvt4(*(const float4*)(kb + (size_t)(m0+r)*HWc + c*4));
        }
        __syncthreads();
        #pragma unroll
        for (int ks = 0; ks < 4; ks++){
            uint32_t a[4][4], bb[4][2];
            #pragma unroll
            for (int mt = 0; mt < 4; mt++){
                int rb = wr*64 + mt*16;
                a[mt][0] = Qs[(ks*8+t4)*136   + rb + g];
                a[mt][1] = Qs[(ks*8+t4)*136   + rb + g + 8];
                a[mt][2] = Qs[(ks*8+t4+4)*136 + rb + g];
                a[mt][3] = Qs[(ks*8+t4+4)*136 + rb + g + 8];
            }
            #pragma unroll
            for (int nt = 0; nt < 4; nt++){
                int nb = wc*32 + nt*8;
                bb[nt][0] = Ks[(ks*8+t4)*136   + nb + g];
                bb[nt][1] = Ks[(ks*8+t4+4)*136 + nb + g];
            }
            #pragma unroll
            for (int mt = 0; mt < 4; mt++)
                #pragma unroll
                for (int nt = 0; nt < 4; nt++)
                    mma_tf32(acc[mt][nt], a[mt], bb[nt][0], bb[nt][1]);
        }
        __syncthreads();
    }
    float* eb = E + (size_t)bl*HWc;
    #pragma unroll
    for (int mt = 0; mt < 4; mt++)
        #pragma unroll
        for (int nt = 0; nt < 4; nt++){
            int row = wr*64 + mt*16 + g;
            int col = wc*32 + nt*8 + t4*2;
            float2 u0 = { acc[mt][nt][0], acc[mt][nt][1] };
            float2 u1 = { acc[mt][nt][2], acc[mt][nt][3] };
            *(float2*)&eb[(size_t)row*128 + col]     = u0;
            *(float2*)&eb[(size_t)(row+8)*128 + col] = u1;
        }
}

// ---------------- joint softmax over 256 scores, in-place fp32 ----------------
__global__ void softmax_kernel(float* __restrict__ eH, float* __restrict__ eW) {
    const int pix  = blockIdx.x*8 + (threadIdx.x >> 5);
    const int lane = threadIdx.x & 31;
    const int w = pix & 127, h = (pix >> 7) & 127, b = pix >> 14;

    float* ph = eH + ((size_t)((b*128 + w)*128 + h))*128 + lane*4;
    float* pw = eW + ((size_t)((b*128 + h)*128 + w))*128 + lane*4;
    float4 vh = *(float4*)ph;
    float4 vw = *(float4*)pw;

    const int d = h - lane*4;
    if (d >= 0 && d < 4) ((float*)&vh)[d] = NEGV;

    float mx = fmaxf(fmaxf(fmaxf(vh.x, vh.y), fmaxf(vh.z, vh.w)),
                     fmaxf(fmaxf(vw.x, vw.y), fmaxf(vw.z, vw.w)));
    #pragma unroll
    for (int o = 16; o; o >>= 1) mx = fmaxf(mx, __shfl_xor_sync(0xffffffffu, mx, o));

    vh.x = __expf(vh.x - mx); vh.y = __expf(vh.y - mx);
    vh.z = __expf(vh.z - mx); vh.w = __expf(vh.w - mx);
    vw.x = __expf(vw.x - mx); vw.y = __expf(vw.y - mx);
    vw.z = __expf(vw.z - mx); vw.w = __expf(vw.w - mx);

    float s = vh.x + vh.y + vh.z + vh.w + vw.x + vw.y + vw.z + vw.w;
    #pragma unroll
    for (int o = 16; o; o >>= 1) s += __shfl_xor_sync(0xffffffffu, s, o);
    const float inv = 1.0f / s;

    vh.x *= inv; vh.y *= inv; vh.z *= inv; vh.w *= inv;
    vw.x *= inv; vw.y *= inv; vw.z *= inv; vw.w *= inv;
    *(float4*)ph = vh;
    *(float4*)pw = vw;
}

// ---------------- apply: Out[c,i] = sum_j V[c,j]*P[i,j], 2-stage async --------
// blockIdx.z: 0 -> (projT, eH) -> outHt ; 1 -> (proj, eW) -> outW(d_out)
__global__ void apply_tf32(const float* __restrict__ proj, const float* __restrict__ projT,
                           const float* __restrict__ eH, const float* __restrict__ eW,
                           float* __restrict__ outHt, float* __restrict__ outW){
    const float* Vfull = blockIdx.z ? proj : projT;
    const float* Pm    = blockIdx.z ? eW : eH;
    float* Outp        = blockIdx.z ? outW : outHt;

    const int bl = blockIdx.y, b = bl >> 7, line = bl & 127;
    const float* Vb = Vfull + ((size_t)(b*PROJ_M + 128 + blockIdx.x*128))*HWc + line*128;
    const float* Pb = Pm + (size_t)bl*HWc;
    float* Ob = Outp + ((size_t)(b*Cch + blockIdx.x*128))*HWc + line*128;

    __shared__ float Vs[2][128*20];   // [c][j] stride 20
    __shared__ float Ps[2][128*20];   // [i][j] stride 20

    const int tid = threadIdx.x, lane = tid & 31, warp = tid >> 5;
    const int g = lane >> 2, t4 = lane & 3;
    const int wr = warp >> 2, wc = warp & 3;

    const float* vrow[2]; const float* prow[2];
    uint32_t vdst[2][2], pdst[2][2];
    #pragma unroll
    for (int i = 0; i < 2; i++){
        int e = tid + i*256;
        int r = e >> 2, c = e & 3;
        vrow[i] = Vb + (size_t)r*HWc + c*4;
        prow[i] = Pb + (size_t)r*128 + c*4;
        vdst[0][i] = sptr(&Vs[0][r*20 + c*4]);
        vdst[1][i] = sptr(&Vs[1][r*20 + c*4]);
        pdst[0][i] = sptr(&Ps[0][r*20 + c*4]);
        pdst[1][i] = sptr(&Ps[1][r*20 + c*4]);
    }

    float acc[4][4][4] = {};
    const int NIT = 128/16;

    #pragma unroll
    for (int i = 0; i < 2; i++){
        cpa16(vdst[0][i], vrow[i]);
        cpa16(pdst[0][i], prow[i]);
    }
    CP_COMMIT();

    for (int it = 0; it < NIT; it++){
        const int cur = it & 1;
        if (it + 1 < NIT){
            const int nxt = cur ^ 1;
            const int j0 = (it+1)*16;
            #pragma unroll
            for (int i = 0; i < 2; i++){
                cpa16(vdst[nxt][i], vrow[i] + j0);
                cpa16(pdst[nxt][i], prow[i] + j0);
            }
            CP_COMMIT();
            CP_WAIT(1);
        } else {
            CP_WAIT(0);
        }
        __syncthreads();
        const float* Vc = Vs[cur];
        const float* Pc = Ps[cur];
        #pragma unroll
        for (int ks = 0; ks < 2; ks++){
            uint32_t a[4][4], bb[4][2];
            #pragma unroll
            for (int mt = 0; mt < 4; mt++){
                int rb = wr*64 + mt*16;
                a[mt][0] = __float_as_uint(Vc[(rb+g)*20   + ks*8 + t4]);
                a[mt][1] = __float_as_uint(Vc[(rb+g+8)*20 + ks*8 + t4]);
                a[mt][2] = __float_as_uint(Vc[(rb+g)*20   + ks*8 + t4 + 4]);
                a[mt][3] = __float_as_uint(Vc[(rb+g+8)*20 + ks*8 + t4 + 4]);
            }
            #pragma unroll
            for (int nt = 0; nt < 4; nt++){
                int nb = wc*32 + nt*8;
                bb[nt][0] = __float_as_uint(Pc[(nb+g)*20 + ks*8 + t4]);
                bb[nt][1] = __float_as_uint(Pc[(nb+g)*20 + ks*8 + t4 + 4]);
            }
            #pragma unroll
            for (int mt = 0; mt < 4; mt++)
                #pragma unroll
                for (int nt = 0; nt < 4; nt++)
                    mma_tf32(acc[mt][nt], a[mt], bb[nt][0], bb[nt][1]);
        }
        __syncthreads();
    }
    #pragma unroll
    for (int mt = 0; mt < 4; mt++)
        #pragma unroll
        for (int nt = 0; nt < 4; nt++){
            int row = wr*64 + mt*16 + g;
            int col = wc*32 + nt*8 + t4*2;
            float2 u0 = { acc[mt][nt][0], acc[mt][nt][1] };
            float2 u1 = { acc[mt][nt][2], acc[mt][nt][3] };
            *(float2*)(Ob + (size_t)row*HWc + col)     = u0;
            *(float2*)(Ob + (size_t)(row+8)*HWc + col) = u1;
        }
}

// ---------------- combine: out = gamma*(outHt^T + outW) + x -------------------
__global__ void combine_kernel(const float* __restrict__ outHt, const float* __restrict__ outW,
                               const float* __restrict__ x, const float* __restrict__ gamma,
                               float* __restrict__ out) {
    __shared__ float t[64][65];
    const size_t p = blockIdx.z;
    const float* hp = outHt + p*HWc;
    const int w0 = blockIdx.x*64, h0 = blockIdx.y*64;
    const int tx = threadIdx.x & 15, ty = threadIdx.x >> 4;
    #pragma unroll
    for (int r = 0; r < 64; r += 16){
        float4 v = *(const float4*)(hp + (size_t)(w0+ty+r)*128 + h0 + tx*4);
        float* d = &t[ty+r][tx*4];
        d[0]=v.x; d[1]=v.y; d[2]=v.z; d[3]=v.w;
    }
    __syncthreads();
    const float g = gamma[0];
    #pragma unroll
    for (int r = 0; r < 64; r += 16){
        const int h = h0 + ty + r;
        const size_t base = p*HWc + (size_t)h*128 + w0 + tx*4;
        float4 xr = *(const float4*)(x + base);
        float4 ow = *(const float4*)(outW + base);
        float4 o;
        o.x = g*(t[tx*4+0][ty+r] + ow.x) + xr.x;
        o.y = g*(t[tx*4+1][ty+r] + ow.y) + xr.y;
        o.z = g*(t[tx*4+2][ty+r] + ow.z) + xr.z;
        o.w = g*(t[tx*4+3][ty+r] + ow.w) + xr.w;
        *(float4*)(out + base) = o;
    }
}

// ---------------------------------------------------------------------------
extern "C" void kernel_launch(void* const* d_in, const int* in_sizes, int n_in,
                              void* d_out, int out_size) {
    (void)in_sizes; (void)n_in; (void)out_size;
    const float* x     = (const float*)d_in[0];
    const float* Wq    = (const float*)d_in[1];
    const float* Wk    = (const float*)d_in[2];
    const float* Wv    = (const float*)d_in[3];
    const float* gamma = (const float*)d_in[4];
    float* out = (float*)d_out;

    float *proj, *projT, *eH, *eW, *outHt;
    cudaGetSymbolAddress((void**)&proj,  g_proj);
    cudaGetSymbolAddress((void**)&projT, g_projT);
    cudaGetSymbolAddress((void**)&eH,    g_eH);
    cudaGetSymbolAddress((void**)&eW,    g_eW);
    cudaGetSymbolAddress((void**)&outHt, g_outHt);

    // 1) fused projection (q|k|v packed: 640 planes per batch)
    proj_tf32<<<dim3(HWc/128, PROJ_M/128, Bsz), 256>>>(Wq, Wk, Wv, x, proj);

    // 2) plane transposes (H<->W for all 640 planes per batch)
    transpose128v<<<dim3(2,2,Bsz*PROJ_M), 256>>>(proj, projT);

    // 3) attention scores (y=0: eH from projT, y=1: eW from proj)
    gram_tf32<<<dim3(Bsz*128, 2), 256>>>(proj, projT, eH, eW);

    // 4) joint softmax (in-place, diag of eH masked)
    softmax_kernel<<<(Bsz*HWc)/8, 256>>>(eH, eW);

    // 5) apply attention (z=0 -> outHt, z=1 -> d_out)
    apply_tf32<<<dim3(Cch/128, Bsz*128, 2), 256>>>(proj, projT, eH, eW, outHt, out);

    // 6) combine
    combine_kernel<<<dim3(2,2,Bsz*Cch), 256>>>(outHt, out, x, gamma, out);
}